// round 2
// baseline (speedup 1.0000x reference)
#include <cuda_runtime.h>
#include <cstdint>

#define MAX_NODES 50000
#define DIM 64

// Scratch: z = x @ W (no bias), needed for the edge gather.
__device__ float g_z[(size_t)MAX_NODES * DIM];

// Packed 2xf32 FMA (sm_100+/sm_103a, PTX-only — ptxas won't auto-fuse)
#define FMA2(d, a, b, c) \
    asm("fma.rn.f32x2 %0, %1, %2, %3;" : "=l"(d) : "l"(a), "l"(b), "l"(c))

// Pack one f32 into both halves of a b64
#define PACK_DUP(u, x) \
    asm("mov.b64 %0, {%1, %1};" : "=l"(u) : "f"(x))

union F2U {
    unsigned long long u;
    float2 f;
};

// ---------------------------------------------------------------------------
// Kernel 1: z = x @ W ; out = z + bias  (self-connection term)
// 256 threads, 128 nodes per block. Each thread: 2 nodes x 16 cols,
// accumulated as 16 packed f32x2 registers via FMA2.
// ---------------------------------------------------------------------------
#define XS_STR4 17   // float4 stride per x row in smem (pad 16->17 kills conflicts)

__global__ void __launch_bounds__(256)
gemm_init_kernel(const float* __restrict__ x,
                 const float* __restrict__ W,
                 const float* __restrict__ bias,
                 float* __restrict__ out,
                 int n)
{
    __shared__ float Ws[64 * 64];            // 16 KB, row k major
    __shared__ float Xs[128 * XS_STR4 * 4];  // 34 KB padded

    const int tid   = threadIdx.x;
    const int node0 = blockIdx.x * 128;

    // Load W: 1024 float4s, coalesced
    {
        const float4* W4  = (const float4*)W;
        float4*       Ws4 = (float4*)Ws;
#pragma unroll
        for (int i = 0; i < 4; i++)
            Ws4[tid + i * 256] = W4[tid + i * 256];
    }
    // Load x tile: 128 rows x 16 float4, into padded smem
    {
        const float4* X4  = (const float4*)x;
        float4*       Xs4 = (float4*)Xs;
#pragma unroll
        for (int i = 0; i < 8; i++) {
            int idx  = tid + i * 256;        // 0..2047
            int r    = idx >> 4;
            int c4   = idx & 15;
            int node = node0 + r;
            float4 v = make_float4(0.f, 0.f, 0.f, 0.f);
            if (node < n) v = X4[(size_t)node * 16 + c4];
            Xs4[r * XS_STR4 + c4] = v;
        }
    }
    __syncthreads();

    const int cg = tid & 3;    // column group: cols [cg*16, cg*16+16)
    const int ng = tid >> 2;   // node pair: nodes {ng*2, ng*2+1} in tile

    unsigned long long acc[2][8];   // [node][pair] -> 2 nodes x 16 cols
#pragma unroll
    for (int a = 0; a < 2; a++)
#pragma unroll
        for (int p = 0; p < 8; p++)
            acc[a][p] = 0ull;       // bit pattern of {0.f, 0.f}

    const float4*     Xs4 = (const float4*)Xs;
    const ulonglong2* Wu  = (const ulonglong2*)Ws;   // [k][8 pairs], pair = 2 cols

#pragma unroll 4
    for (int k4 = 0; k4 < 16; k4++) {
        float4 xv[2];
#pragma unroll
        for (int nl = 0; nl < 2; nl++)
            xv[nl] = Xs4[(ng * 2 + nl) * XS_STR4 + k4];

#pragma unroll
        for (int kk = 0; kk < 4; kk++) {
            const int k = k4 * 4 + kk;
            // my 16 cols of W[k][:] = 8 packed pairs = 4 LDS.128
            ulonglong2 w01 = Wu[k * 16 + cg * 4 + 0];
            ulonglong2 w23 = Wu[k * 16 + cg * 4 + 1];
            ulonglong2 w45 = Wu[k * 16 + cg * 4 + 2];
            ulonglong2 w67 = Wu[k * 16 + cg * 4 + 3];

#pragma unroll
            for (int nl = 0; nl < 2; nl++) {
                float xk = (kk == 0) ? xv[nl].x :
                           (kk == 1) ? xv[nl].y :
                           (kk == 2) ? xv[nl].z : xv[nl].w;
                unsigned long long xp;
                PACK_DUP(xp, xk);
                FMA2(acc[nl][0], xp, w01.x, acc[nl][0]);
                FMA2(acc[nl][1], xp, w01.y, acc[nl][1]);
                FMA2(acc[nl][2], xp, w23.x, acc[nl][2]);
                FMA2(acc[nl][3], xp, w23.y, acc[nl][3]);
                FMA2(acc[nl][4], xp, w45.x, acc[nl][4]);
                FMA2(acc[nl][5], xp, w45.y, acc[nl][5]);
                FMA2(acc[nl][6], xp, w67.x, acc[nl][6]);
                FMA2(acc[nl][7], xp, w67.y, acc[nl][7]);
            }
        }
    }

    // bias for my 16 columns
    float4 bv[4];
    {
        const float4* B4 = (const float4*)bias;
#pragma unroll
        for (int j = 0; j < 4; j++) bv[j] = B4[cg * 4 + j];
    }

#pragma unroll
    for (int nl = 0; nl < 2; nl++) {
        int node = node0 + ng * 2 + nl;
        if (node >= n) continue;
        float4* zrow = (float4*)(g_z + (size_t)node * 64);
        float4* orow = (float4*)(out + (size_t)node * 64);
#pragma unroll
        for (int j = 0; j < 4; j++) {
            F2U lo, hi;
            lo.u = acc[nl][2 * j];
            hi.u = acc[nl][2 * j + 1];
            float4 z = make_float4(lo.f.x, lo.f.y, hi.f.x, hi.f.y);
            zrow[cg * 4 + j] = z;
            orow[cg * 4 + j] = make_float4(z.x + bv[j].x, z.y + bv[j].y,
                                           z.z + bv[j].z, z.w + bv[j].w);
        }
    }
}

// ---------------------------------------------------------------------------
// Kernel 2: edge scatter. out[dst] += z[src] via fire-and-forget vector RED.
// 16 threads per edge; gather via __ldg (L1-cached, saves L2 BW on repeats).
// ---------------------------------------------------------------------------
__global__ void __launch_bounds__(256)
edge_scatter_kernel(const int* __restrict__ src,
                    const int* __restrict__ dst,
                    float* __restrict__ out,
                    int E)
{
    const int64_t t = (int64_t)blockIdx.x * blockDim.x + threadIdx.x;
    const int e = (int)(t >> 4);
    if (e >= E) return;
    const int c = (int)(t & 15) << 2;

    const int s = __ldg(&src[e]);
    const int d = __ldg(&dst[e]);

    const float4 v = __ldg((const float4*)(g_z + (size_t)s * 64 + c));
    float* p = out + (size_t)d * 64 + c;

    asm volatile("red.global.add.v4.f32 [%0], {%1, %2, %3, %4};"
                 :: "l"(p), "f"(v.x), "f"(v.y), "f"(v.z), "f"(v.w)
                 : "memory");
}

// ---------------------------------------------------------------------------
// Kernel 3: finalize. out = relu(out / degree)
// ---------------------------------------------------------------------------
__global__ void __launch_bounds__(256)
finalize_kernel(const float* __restrict__ deg,
                float* __restrict__ out,
                int n)
{
    const int i = blockIdx.x * blockDim.x + threadIdx.x;   // float4 index
    if (i >= n * 16) return;
    const int node = i >> 4;
    const float invd = 1.0f / __ldg(&deg[node]);

    float4 v = ((float4*)out)[i];
    v.x = fmaxf(v.x * invd, 0.f);
    v.y = fmaxf(v.y * invd, 0.f);
    v.z = fmaxf(v.z * invd, 0.f);
    v.w = fmaxf(v.w * invd, 0.f);
    ((float4*)out)[i] = v;
}

// ---------------------------------------------------------------------------
// Launch. Inputs: x, weight, bias, node_degree, edge_src, edge_dst
// ---------------------------------------------------------------------------
extern "C" void kernel_launch(void* const* d_in, const int* in_sizes, int n_in,
                              void* d_out, int out_size)
{
    const float* x      = (const float*)d_in[0];
    const float* weight = (const float*)d_in[1];
    const float* bias   = (const float*)d_in[2];
    const float* deg    = (const float*)d_in[3];
    const int*   esrc   = (const int*)d_in[4];
    const int*   edst   = (const int*)d_in[5];
    float*       out    = (float*)d_out;

    const int n = in_sizes[0] / DIM;
    const int E = in_sizes[4];

    gemm_init_kernel<<<(n + 127) / 128, 256>>>(x, weight, bias, out, n);

    {
        int64_t threads = (int64_t)E * 16;
        int blocks = (int)((threads + 255) / 256);
        edge_scatter_kernel<<<blocks, 256>>>(esrc, edst, out, E);
    }

    {
        int total = n * 16;
        finalize_kernel<<<(total + 255) / 256, 256>>>(deg, out, n);
    }
}

// round 3
// speedup vs baseline: 1.2012x; 1.2012x over previous
#include <cuda_runtime.h>
#include <cstdint>

#define MAX_NODES 50000
#define DIM 64

__device__ float g_z[(size_t)MAX_NODES * DIM];

// Packed 2xf32 FMA (sm_103a, PTX-only)
#define FMA2(d, a, b, c) \
    asm("fma.rn.f32x2 %0, %1, %2, %3;" : "=l"(d) : "l"(a), "l"(b), "l"(c))
#define PACK_DUP(u, x) \
    asm("mov.b64 %0, {%1, %1};" : "=l"(u) : "f"(x))

union F2U { unsigned long long u; float2 f; };

// ---------------------------------------------------------------------------
// Kernel 1: z = x @ W ; out = z + bias
// 256 threads (8 warps), 128 nodes/block.
//   warp w: cg = w & 3 (cols [cg*16, cg*16+16)), half = w >> 2 (node half)
//   lane l: nodes {half*64 + 2l, +1}
// W reads are warp-uniform -> LDS broadcast. x reads are LDS.64 conflict-free
// from a transposed padded tile. Accumulate 2 nodes x 8 col-pairs in FMA2.
// ---------------------------------------------------------------------------
#define XT_STR 130   // floats per k-row in transposed x tile (even, !=0 mod 32)

__global__ void __launch_bounds__(256)
gemm_init_kernel(const float* __restrict__ x,
                 const float* __restrict__ W,
                 const float* __restrict__ bias,
                 float* __restrict__ out,
                 int n)
{
    extern __shared__ float sm[];
    float* Ws  = sm;                 // [64][64]          16 KB
    float* Xt  = sm + 64 * 64;       // [64][XT_STR]      33.3 KB

    const int tid   = threadIdx.x;
    const int node0 = blockIdx.x * 128;

    // Load W coalesced
    {
        const float4* W4  = (const float4*)W;
        float4*       Ws4 = (float4*)Ws;
#pragma unroll
        for (int i = 0; i < 4; i++)
            Ws4[tid + i * 256] = W4[tid + i * 256];
    }
    // Load x tile coalesced, store transposed: Xt[k][node_local]
    {
        const float4* X4 = (const float4*)x;
#pragma unroll
        for (int i = 0; i < 8; i++) {
            int idx  = tid + i * 256;       // 0..2047
            int r    = idx >> 4;            // node_local 0..127
            int c4   = idx & 15;            // float4 col
            int node = node0 + r;
            float4 v = make_float4(0.f, 0.f, 0.f, 0.f);
            if (node < n) v = X4[(size_t)node * 16 + c4];
            Xt[(c4 * 4 + 0) * XT_STR + r] = v.x;
            Xt[(c4 * 4 + 1) * XT_STR + r] = v.y;
            Xt[(c4 * 4 + 2) * XT_STR + r] = v.z;
            Xt[(c4 * 4 + 3) * XT_STR + r] = v.w;
        }
    }
    __syncthreads();

    const int warp = tid >> 5;
    const int lane = tid & 31;
    const int cg   = warp & 3;        // column group (warp-uniform -> broadcast)
    const int half = warp >> 2;       // node half
    const int nl0  = half * 64 + 2 * lane;   // local node of first of pair

    // acc[node 0/1][col-pair 0..7] as packed f32x2
    unsigned long long accA[8], accB[8];
#pragma unroll
    for (int p = 0; p < 8; p++) { accA[p] = 0ull; accB[p] = 0ull; }

    const ulonglong2* Wu = (const ulonglong2*)Ws;   // 4 floats per ulonglong2

#pragma unroll 8
    for (int k = 0; k < 64; k++) {
        // x pair for my 2 nodes (conflict-free LDS.64)
        float2 xp = *(const float2*)&Xt[k * XT_STR + nl0];
        unsigned long long xa, xb;
        PACK_DUP(xa, xp.x);
        PACK_DUP(xb, xp.y);

        // my 16 cols of W[k][:] -- warp-uniform addresses (broadcast)
        ulonglong2 w01 = Wu[k * 16 + cg * 4 + 0];
        ulonglong2 w23 = Wu[k * 16 + cg * 4 + 1];
        ulonglong2 w45 = Wu[k * 16 + cg * 4 + 2];
        ulonglong2 w67 = Wu[k * 16 + cg * 4 + 3];

        FMA2(accA[0], xa, w01.x, accA[0]);
        FMA2(accA[1], xa, w01.y, accA[1]);
        FMA2(accA[2], xa, w23.x, accA[2]);
        FMA2(accA[3], xa, w23.y, accA[3]);
        FMA2(accA[4], xa, w45.x, accA[4]);
        FMA2(accA[5], xa, w45.y, accA[5]);
        FMA2(accA[6], xa, w67.x, accA[6]);
        FMA2(accA[7], xa, w67.y, accA[7]);

        FMA2(accB[0], xb, w01.x, accB[0]);
        FMA2(accB[1], xb, w01.y, accB[1]);
        FMA2(accB[2], xb, w23.x, accB[2]);
        FMA2(accB[3], xb, w23.y, accB[3]);
        FMA2(accB[4], xb, w45.x, accB[4]);
        FMA2(accB[5], xb, w45.y, accB[5]);
        FMA2(accB[6], xb, w67.x, accB[6]);
        FMA2(accB[7], xb, w67.y, accB[7]);
    }

    // bias for my 16 cols
    float4 bv[4];
    {
        const float4* B4 = (const float4*)bias;
#pragma unroll
        for (int q = 0; q < 4; q++) bv[q] = B4[cg * 4 + q];
    }

    // write out both nodes
#pragma unroll
    for (int nn = 0; nn < 2; nn++) {
        int node = node0 + nl0 + nn;
        if (node >= n) continue;
        const unsigned long long* acc = nn ? accB : accA;
        float4* zrow = (float4*)(g_z + (size_t)node * 64);
        float4* orow = (float4*)(out + (size_t)node * 64);
#pragma unroll
        for (int q = 0; q < 4; q++) {
            F2U lo, hi;
            lo.u = acc[2 * q];
            hi.u = acc[2 * q + 1];
            float4 z = make_float4(lo.f.x, lo.f.y, hi.f.x, hi.f.y);
            zrow[cg * 4 + q] = z;
            orow[cg * 4 + q] = make_float4(z.x + bv[q].x, z.y + bv[q].y,
                                           z.z + bv[q].z, z.w + bv[q].w);
        }
    }
}

// ---------------------------------------------------------------------------
// Kernel 2: out[dst] += z[src] via fire-and-forget vector RED (16 thr/edge)
// ---------------------------------------------------------------------------
__global__ void __launch_bounds__(256)
edge_scatter_kernel(const int* __restrict__ src,
                    const int* __restrict__ dst,
                    float* __restrict__ out,
                    int E)
{
    const int64_t t = (int64_t)blockIdx.x * blockDim.x + threadIdx.x;
    const int e = (int)(t >> 4);
    if (e >= E) return;
    const int c = (int)(t & 15) << 2;

    const int s = __ldg(&src[e]);
    const int d = __ldg(&dst[e]);

    const float4 v = __ldg((const float4*)(g_z + (size_t)s * 64 + c));
    float* p = out + (size_t)d * 64 + c;

    asm volatile("red.global.add.v4.f32 [%0], {%1, %2, %3, %4};"
                 :: "l"(p), "f"(v.x), "f"(v.y), "f"(v.z), "f"(v.w)
                 : "memory");
}

// ---------------------------------------------------------------------------
// Kernel 3: out = relu(out / degree)
// ---------------------------------------------------------------------------
__global__ void __launch_bounds__(256)
finalize_kernel(const float* __restrict__ deg,
                float* __restrict__ out,
                int n)
{
    const int i = blockIdx.x * blockDim.x + threadIdx.x;
    if (i >= n * 16) return;
    const int node = i >> 4;
    const float invd = 1.0f / __ldg(&deg[node]);

    float4 v = ((float4*)out)[i];
    v.x = fmaxf(v.x * invd, 0.f);
    v.y = fmaxf(v.y * invd, 0.f);
    v.z = fmaxf(v.z * invd, 0.f);
    v.w = fmaxf(v.w * invd, 0.f);
    ((float4*)out)[i] = v;
}

// ---------------------------------------------------------------------------
extern "C" void kernel_launch(void* const* d_in, const int* in_sizes, int n_in,
                              void* d_out, int out_size)
{
    const float* x      = (const float*)d_in[0];
    const float* weight = (const float*)d_in[1];
    const float* bias   = (const float*)d_in[2];
    const float* deg    = (const float*)d_in[3];
    const int*   esrc   = (const int*)d_in[4];
    const int*   edst   = (const int*)d_in[5];
    float*       out    = (float*)d_out;

    const int n = in_sizes[0] / DIM;
    const int E = in_sizes[4];

    const int smem_bytes = (64 * 64 + 64 * XT_STR) * (int)sizeof(float); // 49664
    static bool attr_set = false;
    if (!attr_set) {
        cudaFuncSetAttribute(gemm_init_kernel,
                             cudaFuncAttributeMaxDynamicSharedMemorySize,
                             smem_bytes);
        attr_set = true;
    }

    gemm_init_kernel<<<(n + 127) / 128, 256, smem_bytes>>>(x, weight, bias, out, n);

    {
        int64_t threads = (int64_t)E * 16;
        int blocks = (int)((threads + 255) / 256);
        edge_scatter_kernel<<<blocks, 256>>>(esrc, edst, out, E);
    }

    {
        int total = n * 16;
        finalize_kernel<<<(total + 255) / 256, 256>>>(deg, out, n);
    }
}

// round 4
// speedup vs baseline: 1.2800x; 1.0656x over previous
#include <cuda_runtime.h>
#include <cstdint>

#define MAX_NODES 50000
#define DIM 64

// agg = x + segment_sum(x[src] -> dst). Initialized by D2D memcpy from x.
__device__ float g_agg[(size_t)MAX_NODES * DIM];

// Packed 2xf32 FMA (sm_103a, PTX-only)
#define FMA2(d, a, b, c) \
    asm("fma.rn.f32x2 %0, %1, %2, %3;" : "=l"(d) : "l"(a), "l"(b), "l"(c))
#define PACK_DUP(u, x) \
    asm("mov.b64 %0, {%1, %1};" : "=l"(u) : "f"(x))

union F2U { unsigned long long u; float2 f; };

// ---------------------------------------------------------------------------
// Kernel 1: edge scatter. agg[dst] += x[src] via fire-and-forget vector RED.
// 16 threads per edge.
// ---------------------------------------------------------------------------
__global__ void __launch_bounds__(256)
edge_scatter_kernel(const float* __restrict__ x,
                    const int* __restrict__ src,
                    const int* __restrict__ dst,
                    int E)
{
    const int64_t t = (int64_t)blockIdx.x * blockDim.x + threadIdx.x;
    const int e = (int)(t >> 4);
    if (e >= E) return;
    const int c = (int)(t & 15) << 2;

    const int s = __ldg(&src[e]);
    const int d = __ldg(&dst[e]);

    const float4 v = __ldg((const float4*)(x + (size_t)s * 64 + c));
    float* p = g_agg + (size_t)d * 64 + c;

    asm volatile("red.global.add.v4.f32 [%0], {%1, %2, %3, %4};"
                 :: "l"(p), "f"(v.x), "f"(v.y), "f"(v.z), "f"(v.w)
                 : "memory");
}

// ---------------------------------------------------------------------------
// Kernel 2 (fused): out = relu((agg @ W + bias) / deg)
// 128 threads (4 warps), 64 nodes per block.
//   warp w = column group cg (cols [cg*16, cg*16+16)) -> W reads broadcast
//   lane l = nodes {2l, 2l+1} -> x reads conflict-free LDS.64
// ---------------------------------------------------------------------------
#define XT_STR 66   // floats per k-row of transposed tile (even -> aligned f2)

__global__ void __launch_bounds__(128)
gemm_fused_kernel(const float* __restrict__ W,
                  const float* __restrict__ bias,
                  const float* __restrict__ deg,
                  float* __restrict__ out,
                  int n)
{
    __shared__ float Ws[64 * 64];        // 16 KB
    __shared__ float Xt[64 * XT_STR];    // 16.5 KB  (transposed agg tile)

    const int tid   = threadIdx.x;
    const int node0 = blockIdx.x * 64;

    // Load W coalesced (1024 float4s)
    {
        const float4* W4  = (const float4*)W;
        float4*       Ws4 = (float4*)Ws;
#pragma unroll
        for (int i = 0; i < 8; i++)
            Ws4[tid + i * 128] = W4[tid + i * 128];
    }
    // Load agg tile (64 rows x 16 float4), store transposed Xt[k][node]
    {
        const float4* A4 = (const float4*)g_agg;
#pragma unroll
        for (int i = 0; i < 8; i++) {
            int idx  = tid + i * 128;       // 0..1023
            int r    = idx >> 4;            // node_local 0..63
            int c4   = idx & 15;
            int node = node0 + r;
            float4 v = make_float4(0.f, 0.f, 0.f, 0.f);
            if (node < n) v = A4[(size_t)node * 16 + c4];
            Xt[(c4 * 4 + 0) * XT_STR + r] = v.x;
            Xt[(c4 * 4 + 1) * XT_STR + r] = v.y;
            Xt[(c4 * 4 + 2) * XT_STR + r] = v.z;
            Xt[(c4 * 4 + 3) * XT_STR + r] = v.w;
        }
    }
    __syncthreads();

    const int cg   = tid >> 5;          // warp = column group (uniform)
    const int lane = tid & 31;
    const int nl0  = 2 * lane;          // first of my node pair

    unsigned long long accA[8], accB[8];
#pragma unroll
    for (int p = 0; p < 8; p++) { accA[p] = 0ull; accB[p] = 0ull; }

    const ulonglong2* Wu = (const ulonglong2*)Ws;

#pragma unroll 8
    for (int k = 0; k < 64; k++) {
        float2 xp = *(const float2*)&Xt[k * XT_STR + nl0];
        unsigned long long xa, xb;
        PACK_DUP(xa, xp.x);
        PACK_DUP(xb, xp.y);

        ulonglong2 w01 = Wu[k * 16 + cg * 4 + 0];
        ulonglong2 w23 = Wu[k * 16 + cg * 4 + 1];
        ulonglong2 w45 = Wu[k * 16 + cg * 4 + 2];
        ulonglong2 w67 = Wu[k * 16 + cg * 4 + 3];

        FMA2(accA[0], xa, w01.x, accA[0]);
        FMA2(accA[1], xa, w01.y, accA[1]);
        FMA2(accA[2], xa, w23.x, accA[2]);
        FMA2(accA[3], xa, w23.y, accA[3]);
        FMA2(accA[4], xa, w45.x, accA[4]);
        FMA2(accA[5], xa, w45.y, accA[5]);
        FMA2(accA[6], xa, w67.x, accA[6]);
        FMA2(accA[7], xa, w67.y, accA[7]);

        FMA2(accB[0], xb, w01.x, accB[0]);
        FMA2(accB[1], xb, w01.y, accB[1]);
        FMA2(accB[2], xb, w23.x, accB[2]);
        FMA2(accB[3], xb, w23.y, accB[3]);
        FMA2(accB[4], xb, w45.x, accB[4]);
        FMA2(accB[5], xb, w45.y, accB[5]);
        FMA2(accB[6], xb, w67.x, accB[6]);
        FMA2(accB[7], xb, w67.y, accB[7]);
    }

    // bias for my 16 cols
    float4 bv[4];
    {
        const float4* B4 = (const float4*)bias;
#pragma unroll
        for (int q = 0; q < 4; q++) bv[q] = B4[cg * 4 + q];
    }

    // epilogue: (acc + bias) * (1/deg), relu, store
#pragma unroll
    for (int nn = 0; nn < 2; nn++) {
        int node = node0 + nl0 + nn;
        if (node >= n) continue;
        const unsigned long long* acc = nn ? accB : accA;
        const float invd = 1.0f / __ldg(&deg[node]);
        float4* orow = (float4*)(out + (size_t)node * 64);
#pragma unroll
        for (int q = 0; q < 4; q++) {
            F2U lo, hi;
            lo.u = acc[2 * q];
            hi.u = acc[2 * q + 1];
            float4 o;
            o.x = fmaxf((lo.f.x + bv[q].x) * invd, 0.f);
            o.y = fmaxf((lo.f.y + bv[q].y) * invd, 0.f);
            o.z = fmaxf((hi.f.x + bv[q].z) * invd, 0.f);
            o.w = fmaxf((hi.f.y + bv[q].w) * invd, 0.f);
            orow[cg * 4 + q] = o;
        }
    }
}

// ---------------------------------------------------------------------------
// Launch. Inputs: x, weight, bias, node_degree, edge_src, edge_dst
// ---------------------------------------------------------------------------
extern "C" void kernel_launch(void* const* d_in, const int* in_sizes, int n_in,
                              void* d_out, int out_size)
{
    const float* x      = (const float*)d_in[0];
    const float* weight = (const float*)d_in[1];
    const float* bias   = (const float*)d_in[2];
    const float* deg    = (const float*)d_in[3];
    const int*   esrc   = (const int*)d_in[4];
    const int*   edst   = (const int*)d_in[5];
    float*       out    = (float*)d_out;

    const int n = in_sizes[0] / DIM;
    const int E = in_sizes[4];

    // 1) agg = x  (self connection), D2D async copy into __device__ scratch
    cudaMemcpyToSymbolAsync(g_agg, x, (size_t)n * DIM * sizeof(float),
                            0, cudaMemcpyDeviceToDevice, 0);

    // 2) agg[dst] += x[src] over all edges
    {
        int64_t threads = (int64_t)E * 16;
        int blocks = (int)((threads + 255) / 256);
        edge_scatter_kernel<<<blocks, 256>>>(x, esrc, edst, E);
    }

    // 3) out = relu((agg @ W + b) / deg)
    gemm_fused_kernel<<<(n + 63) / 64, 128>>>(weight, bias, deg, out, n);
}